// round 12
// baseline (speedup 1.0000x reference)
#include <cuda_runtime.h>

// KnnLoss via anisotropic spatial grid, warp-per-query, segmented packed sweep:
// B=4, N=8192, C=3, K=16, RADIUS=0.5, L2.
// Out-of-radius neighbors are replaced by self (zero contribution) => only
// the <=16 nearest in-radius neighbors matter.
// Grid: z at 0.5 (16), y at 0.25 (32), x at 0.125 (64). Per z-slab the
// y-range is the exact circular bound |dy| <= sqrt(GATE2 - dz2); per (z,y)
// row the x-window is |dx| <= sqrt(GATE2 - dz2 - by^2). All bounds use band
// (lower-bound) distances + round-up sqrt + slack => provable superset of
// the in-radius set under the clamped monotone cell maps.
// Kernel 1 (4 CTAs): histogram (128 KB dyn smem) + conflict-free warp-chunk
//   scan + register scatter (points loaded as contiguous float4s).
// Kernel 2: per query-warp: 15 lanes (3 slabs x 5 rows) compute row runs in
//   parallel; shfl scan concatenates them into one packed index space swept
//   in fully packed 32-lane iterations (monotone segment cursor). In-radius
//   keys (17-bit quantized d2 | 13-bit idx => unique, tie = lower idx like
//   top_k) are ballot-compacted; top-16 via register tournament (fast path
//   cnt<=16); parallel flow norms; last CTA reduces partials.

#define BB 4
#define NN 8192
#define KK 16
#define GZ 16
#define GYF 32
#define GX 64
#define NCELLS (GZ * GYF * GX)       // 32768
#define TPB 256
#define WPB (TPB / 32)               // 8 queries per CTA
#define CAP 512
#define NPART (NN / WPB)             // 1024 CTAs per batch
#define NCTAS (BB * NPART)           // 4096
#define IMAX 0x7FFFFFFF
#define RGATE 0.2500001f             // keep d2 whose sqrt rounds to <= 0.5
#define GATE2 0.2500002f             // prune bound (extra fp slack)

__device__ int g_offsets[BB * (NCELLS + 1)];
__device__ float4 g_sorted[BB * NN + 64];  // pad: unpredicated sweep loads
__device__ float g_partials[NCTAS];
__device__ int g_done;  // zero-init; reset by last CTA each run

__device__ __forceinline__ int cell_z(float v) {
    int c = (int)floorf((v + 4.0f) * 2.0f);
    return min(max(c, 0), GZ - 1);
}
__device__ __forceinline__ int cell_y(float v) {
    int c = (int)floorf((v + 4.0f) * 4.0f);
    return min(max(c, 0), GYF - 1);
}
__device__ __forceinline__ int cell_x(float v) {
    int c = (int)floorf((v + 4.0f) * 8.0f);
    return min(max(c, 0), GX - 1);
}

#define CSWAP(a, b) { int t_ = min(a, b); b = max(a, b); a = t_; }

// ---- 1. fused grid build: histogram + scan + scatter (one CTA per batch) ---
#define PPT (NN / 1024)       // 8 points per thread (contiguous)
#define CPW (NCELLS / 32)     // 1024 cells per warp
#define CHUNKS (CPW / 32)     // 32 coalesced chunks of 32
__global__ __launch_bounds__(1024) void grid_build_kernel(
    const float* __restrict__ pc) {
    extern __shared__ int hist[];  // NCELLS ints = 128 KB (dynamic)
    __shared__ int wtot[32];
    const int b = blockIdx.x, t = threadIdx.x;
    const int lane = t & 31, w = t >> 5;

#pragma unroll
    for (int i = 0; i < NCELLS / 1024; ++i) hist[t + i * 1024] = 0;
    __syncthreads();

    // Load 8 contiguous points (96B) as 6 float4s.
    const float4* pcv =
        (const float4*)(pc + (size_t)b * NN * 3) + (size_t)t * 6;
    float f[24];
#pragma unroll
    for (int j = 0; j < 6; ++j) {
        float4 q = pcv[j];
        f[4 * j + 0] = q.x; f[4 * j + 1] = q.y;
        f[4 * j + 2] = q.z; f[4 * j + 3] = q.w;
    }
    int cell[PPT], rank[PPT];
#pragma unroll
    for (int i = 0; i < PPT; ++i) {
        cell[i] = (cell_z(f[3 * i + 2]) * GYF + cell_y(f[3 * i + 1])) * GX +
                  cell_x(f[3 * i + 0]);
        rank[i] = atomicAdd(&hist[cell[i]], 1);
    }
    __syncthreads();

    // Conflict-free exclusive scan: warp w owns cells [w*1024, w*1024+1024),
    // processed as 32 coalesced chunks of 32 with a running carry.
    const int wbase = w * CPW;
    int carry = 0;
#pragma unroll
    for (int i = 0; i < CHUNKS; ++i) {
        int idx = wbase + i * 32 + lane;
        int v = hist[idx];
        int s = v;
#pragma unroll
        for (int o = 1; o < 32; o <<= 1) {
            int u = __shfl_up_sync(0xFFFFFFFFu, s, o);
            if (lane >= o) s += u;
        }
        hist[idx] = s - v + carry;  // exclusive within warp region
        carry += __shfl_sync(0xFFFFFFFFu, s, 31);
    }
    if (lane == 0) wtot[w] = carry;
    __syncthreads();
    if (w == 0) {
        int x = wtot[lane];
#pragma unroll
        for (int o = 1; o < 32; o <<= 1) {
            int u = __shfl_up_sync(0xFFFFFFFFu, x, o);
            if (lane >= o) x += u;
        }
        wtot[lane] = x;
    }
    __syncthreads();
    const int woff = (w > 0) ? wtot[w - 1] : 0;
    int* gob = g_offsets + b * (NCELLS + 1);
#pragma unroll
    for (int i = 0; i < CHUNKS; ++i) {
        int idx = wbase + i * 32 + lane;
        int val = hist[idx] + woff;
        hist[idx] = val;
        gob[idx] = val;
    }
    if (t == 0) gob[NCELLS] = NN;  // grand total is exactly NN
    __syncthreads();

    // Scatter from registers.
    float4* sbb = g_sorted + b * NN;
#pragma unroll
    for (int i = 0; i < PPT; ++i) {
        int pos = hist[cell[i]] + rank[i];
        sbb[pos] = make_float4(f[3 * i], f[3 * i + 1], f[3 * i + 2],
                               __int_as_float(t * PPT + i));
    }
}

// ---- 2. main: warp per query; last CTA finalizes ----
__global__ __launch_bounds__(TPB, 8) void knn_loss_kernel(
    const float* __restrict__ flow, float* __restrict__ out) {
    __shared__ int buf[WPB][CAP];
    __shared__ int cseg[WPB][16];  // cumulative segment ends (IMAX pad)
    __shared__ int bseg[WPB][16];  // rebased segment starts
    __shared__ float cpart[WPB];
    __shared__ int lastflag;

    const int b = blockIdx.y;
    const int w = threadIdx.x >> 5;
    const int lane = threadIdx.x & 31;
    const unsigned lt_mask = (1u << lane) - 1u;
    const int sp = blockIdx.x * WPB + w;
    int* __restrict__ bw = buf[w];
    const float4* __restrict__ sb = g_sorted + b * NN;
    const int* __restrict__ ob = g_offsets + b * (NCELLS + 1);
    const float* __restrict__ flb = flow + (size_t)b * NN * 3;

    const float4 me = sb[sp];  // broadcast
    const int qi = __float_as_int(me.w);
    const int cz = cell_z(me.z);
    const float fz = fmaf((float)cz, -0.5f, me.z + 4.0f);  // pos in z-cell

    // 15 lanes (3 z-slabs x 5 y-rows) compute row runs [s0, s0+len) in
    // parallel. Per slab: exact circular y-window; per row: exact x-chord.
    {
        const int dzI = lane / 5;       // 0..2 (lane < 15)
        const int j = lane - dzI * 5;   // 0..4
        const int z2 = cz + dzI - 1;
        bool ok = (lane < 15) && ((unsigned)z2 < (unsigned)GZ);
        // Band distance^2 toward this z-slab (lower bound on (dz)^2).
        float dz2 = (dzI == 1) ? 0.0f
                               : ((dzI == 0) ? fz * fz
                                             : (0.5f - fz) * (0.5f - fz));
        ok = ok && (dz2 <= GATE2);
        int s0 = 0, len = 0;
        if (ok) {
            float wy = __fsqrt_ru(GATE2 - dz2) + 4e-6f;
            int ylo = cell_y(me.y - wy);
            int yspan = cell_y(me.y + wy) - ylo;  // <= 4
            if (j <= yspan) {
                int y2 = ylo + j;
                // Band distance from qy to y-cell [y2*0.25-4, +0.25).
                float tt = fmaf((float)y2, -0.25f, me.y + 4.0f);
                float by = fmaxf(fmaxf(-tt, tt - 0.25f), 0.0f);
                float rd2 = fmaf(by, by, dz2);
                if (rd2 <= GATE2) {
                    float wx = __fsqrt_ru(GATE2 - rd2) + 4e-6f;
                    int xl = cell_x(me.x - wx);
                    int xh = cell_x(me.x + wx);
                    int base = (z2 * GYF + y2) * GX;
                    s0 = ob[base + xl];
                    len = ob[base + xh + 1] - s0;
                }
            }
        }
        int c = len;  // inclusive scan over lanes 0..15 (len=0 for >=15)
#pragma unroll
        for (int o = 1; o < 16; o <<= 1) {
            int u = __shfl_up_sync(0xFFFFFFFFu, c, o);
            if (lane >= o) c += u;
        }
        if (lane < 16) {
            cseg[w][lane] = (lane < 15) ? c : IMAX;
            bseg[w][lane] = (lane < 15) ? (s0 - (c - len)) : 0;
        }
    }
    __syncwarp();
    const int L = cseg[w][14];  // total candidates (broadcast LDS)

    // Packed sweep over the concatenated index space, fully 32-wide.
    int cnt = 0;  // warp-uniform
    {
        int r = 0;
        int cend = cseg[w][0];
        int kbase = bseg[w][0];
        const int nit = (L + 31) >> 5;
        for (int it = 0; it < nit; ++it) {
            int g = (it << 5) + lane;
            while (g >= cend) {  // monotone cursor: <=15 advances total/lane
                ++r;
                cend = cseg[w][r];
                kbase = bseg[w][r];
            }
            int k = kbase + g;  // invalid lanes (g>=L): r=15 => k=g, safe
            float4 p = sb[k];
            float ddx = me.x - p.x;
            float ddy = me.y - p.y;
            float ddz = me.z - p.z;
            float d2 = fmaf(ddx, ddx, fmaf(ddy, ddy, ddz * ddz));
            bool inr = (d2 < RGATE) & (g < L);
            unsigned mask = __ballot_sync(0xFFFFFFFFu, inr);
            if (inr) {
                int key = ((int)(d2 * 262144.0f) << 13) | __float_as_int(p.w);
                int pos = cnt + __popc(mask & lt_mask);
                if (pos < CAP) bw[pos] = key;
            }
            cnt += __popc(mask);
        }
    }
    cnt = min(cnt, CAP);
    __syncwarp();

    // Phase 2: top-16 selection; winners parked one per lane.
    const int R = min(cnt, KK);
    int selkey = IMAX;
    if (cnt <= KK) {
        selkey = (lane < cnt) ? bw[lane] : IMAX;
    } else if (cnt <= 64) {
        int v0 = (lane < cnt) ? bw[lane] : IMAX;
        int v1 = (lane + 32 < cnt) ? bw[lane + 32] : IMAX;
        CSWAP(v0, v1);
        for (int r = 0; r < R; ++r) {
            int gmin = __reduce_min_sync(0xFFFFFFFFu, v0);
            bool won = (v0 == gmin);  // unique keys => exactly one winner
            v0 = won ? v1 : v0;
            v1 = won ? IMAX : v1;
            if (lane == r) selkey = gmin;
        }
    } else if (cnt <= 128) {
        int v0 = (lane < cnt) ? bw[lane] : IMAX;
        int v1 = (lane + 32 < cnt) ? bw[lane + 32] : IMAX;
        int v2 = (lane + 64 < cnt) ? bw[lane + 64] : IMAX;
        int v3 = (lane + 96 < cnt) ? bw[lane + 96] : IMAX;
        CSWAP(v0, v1); CSWAP(v2, v3); CSWAP(v0, v2); CSWAP(v1, v3);
        CSWAP(v1, v2);
        for (int r = 0; r < R; ++r) {
            int gmin = __reduce_min_sync(0xFFFFFFFFu, v0);
            bool won = (v0 == gmin);
            v0 = won ? v1 : v0;
            v1 = won ? v2 : v1;
            v2 = won ? v3 : v2;
            v3 = won ? IMAX : v3;
            if (lane == r) selkey = gmin;
        }
    } else if (cnt <= 256) {
        int v0 = (lane < cnt) ? bw[lane] : IMAX;
        int v1 = (lane + 32 < cnt) ? bw[lane + 32] : IMAX;
        int v2 = (lane + 64 < cnt) ? bw[lane + 64] : IMAX;
        int v3 = (lane + 96 < cnt) ? bw[lane + 96] : IMAX;
        int v4 = (lane + 128 < cnt) ? bw[lane + 128] : IMAX;
        int v5 = (lane + 160 < cnt) ? bw[lane + 160] : IMAX;
        int v6 = (lane + 192 < cnt) ? bw[lane + 192] : IMAX;
        int v7 = (lane + 224 < cnt) ? bw[lane + 224] : IMAX;
        // Batcher odd-even merge sort for 8.
        CSWAP(v0, v1); CSWAP(v2, v3); CSWAP(v4, v5); CSWAP(v6, v7);
        CSWAP(v0, v2); CSWAP(v1, v3); CSWAP(v4, v6); CSWAP(v5, v7);
        CSWAP(v1, v2); CSWAP(v5, v6);
        CSWAP(v0, v4); CSWAP(v1, v5); CSWAP(v2, v6); CSWAP(v3, v7);
        CSWAP(v2, v4); CSWAP(v3, v5);
        CSWAP(v1, v2); CSWAP(v3, v4); CSWAP(v5, v6);
        for (int r = 0; r < R; ++r) {
            int gmin = __reduce_min_sync(0xFFFFFFFFu, v0);
            bool won = (v0 == gmin);
            v0 = won ? v1 : v0;
            v1 = won ? v2 : v1;
            v2 = won ? v3 : v2;
            v3 = won ? v4 : v3;
            v4 = won ? v5 : v4;
            v5 = won ? v6 : v5;
            v6 = won ? v7 : v6;
            v7 = won ? IMAX : v7;
            if (lane == r) selkey = gmin;
        }
    } else {
        const int P = (cnt + 31) >> 5;
        for (int r = 0; r < R; ++r) {
            int mymin = IMAX, myidx = 0;
            for (int i = 0; i < P; ++i) {
                int k = lane + (i << 5);
                int vv = (k < cnt) ? bw[k] : IMAX;
                if (vv < mymin) { mymin = vv; myidx = k; }
            }
            int gmin = __reduce_min_sync(0xFFFFFFFFu, mymin);
            if (mymin == gmin && gmin != IMAX) bw[myidx] = IMAX;
            if (lane == r) selkey = gmin;
            __syncwarp();
        }
    }

    // Phase 3: selected lanes compute flow norms; warp + CTA reduce.
    float acc = 0.0f;
    if (selkey != IMAX) {
        const int j = selkey & (NN - 1);  // j==qi (self) => exact 0
        float ddx = flb[3 * qi + 0] - flb[3 * j + 0];
        float ddy = flb[3 * qi + 1] - flb[3 * j + 1];
        float ddz = flb[3 * qi + 2] - flb[3 * j + 2];
        acc = __fsqrt_rn(fmaf(ddx, ddx, fmaf(ddy, ddy, ddz * ddz)));
    }
#pragma unroll
    for (int o = 16; o > 0; o >>= 1)
        acc += __shfl_xor_sync(0xFFFFFFFFu, acc, o);
    if (lane == 0) cpart[w] = acc;
    __syncthreads();
    if (threadIdx.x == 0) {
        float s = 0.0f;
#pragma unroll
        for (int i = 0; i < WPB; ++i) s += cpart[i];
        g_partials[b * NPART + blockIdx.x] = s;
        __threadfence();
        int d = atomicAdd(&g_done, 1);
        lastflag = (d == NCTAS - 1) ? 1 : 0;
    }
    __syncthreads();

    // Last CTA: deterministic fixed-order reduction of all partials.
    if (lastflag) {
        __threadfence();
        float s2 = 0.0f;
#pragma unroll
        for (int i = 0; i < NCTAS / TPB; ++i)
            s2 += g_partials[threadIdx.x + i * TPB];
#pragma unroll
        for (int o = 16; o > 0; o >>= 1)
            s2 += __shfl_xor_sync(0xFFFFFFFFu, s2, o);
        if (lane == 0) cpart[w] = s2;
        __syncthreads();
        if (threadIdx.x == 0) {
            float s3 = 0.0f;
#pragma unroll
            for (int i = 0; i < WPB; ++i) s3 += cpart[i];
            out[0] = s3 * (1.0f / (float)((size_t)BB * NN * KK));
            g_done = 0;  // reset for next graph replay
        }
    }
}

extern "C" void kernel_launch(void* const* d_in, const int* in_sizes, int n_in,
                              void* d_out, int out_size) {
    const float* pc = (const float*)d_in[0];
    const float* flow = (const float*)d_in[1];

    cudaFuncSetAttribute(grid_build_kernel,
                         cudaFuncAttributeMaxDynamicSharedMemorySize,
                         NCELLS * (int)sizeof(int));

    grid_build_kernel<<<BB, 1024, NCELLS * sizeof(int)>>>(pc);
    dim3 grid(NN / WPB, BB);
    knn_loss_kernel<<<grid, TPB>>>(flow, (float*)d_out);
}

// round 13
// speedup vs baseline: 1.0700x; 1.0700x over previous
#include <cuda_runtime.h>

// KnnLoss via anisotropic spatial grid, warp-per-query, segmented packed sweep:
// B=4, N=8192, C=3, K=16, RADIUS=0.5, L2.
// Out-of-radius neighbors are replaced by self (zero contribution) => only
// the <=16 nearest in-radius neighbors matter.
// Grid: y,z at 0.5 (16 cells), x at 0.125 (64 cells); per (z,y) row the
// x-window is the exact circular bound |dx| <= sqrt(GATE2 - rd2) (+slack).
// Build is chip-parallel:
//   K1 (64 CTAs): per-point cell + global-atomic histogram with rank
//      capture; the last-arriving CTA of each batch scans that batch's
//      16K counts into offsets (4 scans run concurrently).
//   K2 (64 CTAs): scatter points into cell-sorted order (atomic-free, rank
//      precomputed) and re-zero g_counts for the next graph replay.
//   K3 (main, unchanged from R11): per query-warp, lanes 0..8 compute the 9
//      row runs in parallel; shfl scan concatenates them into one packed
//      index space swept in fully packed 32-lane iterations (monotone
//      segment cursor). In-radius keys (17-bit quantized d2 | 13-bit idx =>
//      unique, tie = lower idx like top_k) are ballot-compacted; top-16 via
//      register tournament; parallel flow norms; last CTA reduces.

#define BB 4
#define NN 8192
#define KK 16
#define GY 16
#define GX 64
#define NCELLS (GY * GY * GX)        // 16384
#define TPB 256
#define WPB (TPB / 32)               // 8 queries per CTA
#define CAP 512
#define NPART (NN / WPB)             // 1024 CTAs per batch
#define NCTAS (BB * NPART)           // 4096
#define IMAX 0x7FFFFFFF
#define RGATE 0.2500001f             // keep d2 whose sqrt rounds to <= 0.5
#define GATE2 0.2500002f             // prune bound (extra fp slack)

#define HTPB 512                     // build kernels: 512 thr, 64 CTAs
#define HCTAS (BB * NN / HTPB)       // 64
#define CTAS_PER_B (HCTAS / BB)      // 16

__device__ int g_cellrank[BB * NN];  // cell (14b) | rank << 14
__device__ int g_counts[BB * NCELLS];      // zero-init; re-zeroed by scatter
__device__ int g_offsets[BB * (NCELLS + 1)];
__device__ float4 g_sorted[BB * NN + 64];  // pad: unpredicated sweep loads
__device__ float g_partials[NCTAS];
__device__ int g_bdone[BB];  // per-batch hist tickets; self-reset
__device__ int g_done;       // main-kernel ticket; self-reset

__device__ __forceinline__ int cell_yz(float v) {
    int c = (int)floorf((v + 4.0f) * 2.0f);
    return min(max(c, 0), GY - 1);
}
__device__ __forceinline__ int cell_x(float v) {
    int c = (int)floorf((v + 4.0f) * 8.0f);
    return min(max(c, 0), GX - 1);
}

#define CSWAP(a, b) { int t_ = min(a, b); b = max(a, b); a = t_; }

// ---- K1: histogram + rank; last CTA per batch scans its batch ----
__global__ __launch_bounds__(HTPB) void hist_kernel(
    const float* __restrict__ pc) {
    __shared__ int wtot[16];
    __shared__ int lastflag;
    const int t = threadIdx.x;
    const int lane = t & 31, w = t >> 5;
    const int gid = blockIdx.x * HTPB + t;
    const int b = blockIdx.x / CTAS_PER_B;  // CTA handles one batch only
    const int n = gid & (NN - 1);

    const float* p = pc + (size_t)b * NN * 3 + 3 * n;
    int cell = (cell_yz(p[2]) * GY + cell_yz(p[1])) * GX + cell_x(p[0]);
    int rank = atomicAdd(&g_counts[b * NCELLS + cell], 1);
    g_cellrank[gid] = cell | (rank << 14);

    // Per-batch ticket: the 16th CTA of this batch scans the batch.
    __threadfence();
    __syncthreads();
    if (t == 0)
        lastflag = (atomicAdd(&g_bdone[b], 1) == CTAS_PER_B - 1) ? 1 : 0;
    __syncthreads();
    if (!lastflag) return;
    __threadfence();

    // Scan 16384 counts with 512 threads: warp w owns cells
    // [w*1024, w*1024+1024) as 32 coalesced chunks of 32.
    const int* cnt = g_counts + b * NCELLS;
    int* off = g_offsets + b * (NCELLS + 1);
    const int wbase = w * 1024;

    // Pass A: warp totals.
    int psum = 0;
#pragma unroll
    for (int i = 0; i < 32; ++i) psum += cnt[wbase + i * 32 + lane];
#pragma unroll
    for (int o = 16; o > 0; o >>= 1)
        psum += __shfl_xor_sync(0xFFFFFFFFu, psum, o);
    if (lane == 0) wtot[w] = psum;
    __syncthreads();
    if (w == 0 && lane < 16) {
        int x = wtot[lane];
#pragma unroll
        for (int o = 1; o < 16; o <<= 1) {
            int u = __shfl_up_sync(0x0000FFFFu, x, o);
            if (lane >= o) x += u;
        }
        wtot[lane] = x;
    }
    __syncthreads();

    // Pass B: running exclusive scan, coalesced writes.
    int carry = (w > 0) ? wtot[w - 1] : 0;
#pragma unroll
    for (int i = 0; i < 32; ++i) {
        int idx = wbase + i * 32 + lane;
        int v = cnt[idx];
        int s = v;
#pragma unroll
        for (int o = 1; o < 32; o <<= 1) {
            int u = __shfl_up_sync(0xFFFFFFFFu, s, o);
            if (lane >= o) s += u;
        }
        off[idx] = s - v + carry;
        carry += __shfl_sync(0xFFFFFFFFu, s, 31);
    }
    if (t == 0) {
        off[NCELLS] = NN;  // grand total is exactly NN
        g_bdone[b] = 0;    // reset ticket for next replay
    }
}

// ---- K2: scatter into cell-sorted order; re-zero counts for next run ----
__global__ __launch_bounds__(HTPB) void scatter_kernel(
    const float* __restrict__ pc) {
    const int gid = blockIdx.x * HTPB + threadIdx.x;
    const int b = blockIdx.x / CTAS_PER_B;
    const int n = gid & (NN - 1);
    const float* p = pc + (size_t)b * NN * 3 + 3 * n;
    int cr = g_cellrank[gid];
    int cell = cr & (NCELLS - 1), rank = cr >> 14;
    int pos = g_offsets[b * (NCELLS + 1) + cell] + rank;
    g_sorted[b * NN + pos] = make_float4(p[0], p[1], p[2],
                                         __int_as_float(n));
    // Re-zero counts (2 per thread) so the next replay starts clean.
    g_counts[gid] = 0;
    g_counts[gid + BB * NN] = 0;
}

// ---- K3: main, warp per query; last CTA finalizes (R11 verbatim) ----
__global__ __launch_bounds__(TPB, 8) void knn_loss_kernel(
    const float* __restrict__ flow, float* __restrict__ out) {
    __shared__ int buf[WPB][CAP];
    __shared__ int cseg[WPB][16];  // cumulative segment ends (IMAX pad)
    __shared__ int bseg[WPB][16];  // rebased segment starts
    __shared__ float cpart[WPB];
    __shared__ int lastflag;

    const int b = blockIdx.y;
    const int w = threadIdx.x >> 5;
    const int lane = threadIdx.x & 31;
    const unsigned lt_mask = (1u << lane) - 1u;
    const int sp = blockIdx.x * WPB + w;
    int* __restrict__ bw = buf[w];
    const float4* __restrict__ sb = g_sorted + b * NN;
    const int* __restrict__ ob = g_offsets + b * (NCELLS + 1);
    const float* __restrict__ flb = flow + (size_t)b * NN * 3;

    const float4 me = sb[sp];  // broadcast
    const int qi = __float_as_int(me.w);
    const int cy = cell_yz(me.y), cz = cell_yz(me.z);
    const float fy = fmaf((float)cy, -0.5f, me.y + 4.0f);
    const float fz = fmaf((float)cz, -0.5f, me.z + 4.0f);

    // Lanes 0..8 compute their row's run [s0, s0+len) in parallel.
    {
        int dz = lane / 3 - 1, dy = lane - (lane / 3) * 3 - 1;
        int z2 = cz + dz, y2 = cy + dy;
        bool okrow = (lane < 9) && ((unsigned)z2 < (unsigned)GY) &&
                     ((unsigned)y2 < (unsigned)GY);
        float dy2 = (dy == 0) ? 0.0f
                              : ((dy < 0) ? fy * fy
                                          : (0.5f - fy) * (0.5f - fy));
        float dz2 = (dz == 0) ? 0.0f
                              : ((dz < 0) ? fz * fz
                                          : (0.5f - fz) * (0.5f - fz));
        float rd2 = dy2 + dz2;
        okrow = okrow && (rd2 <= GATE2);
        int s0 = 0, len = 0;
        if (okrow) {
            // Exact circular x-window (round-up + slack: clamped monotone
            // cell map provably covers the in-radius disk).
            float ww = __fsqrt_ru(GATE2 - rd2) + 4e-6f;
            int xl = cell_x(me.x - ww);
            int xh = cell_x(me.x + ww);
            int base = (z2 * GY + y2) * GX;
            s0 = ob[base + xl];
            len = ob[base + xh + 1] - s0;
        }
        int c = len;  // inclusive scan over the warp (lanes >=9 have len 0)
#pragma unroll
        for (int o = 1; o < 16; o <<= 1) {
            int u = __shfl_up_sync(0xFFFFFFFFu, c, o);
            if (lane >= o) c += u;
        }
        if (lane < 16) {
            cseg[w][lane] = (lane < 9) ? c : IMAX;
            bseg[w][lane] = (lane < 9) ? (s0 - (c - len)) : 0;
        }
    }
    __syncwarp();
    const int L = cseg[w][8];  // total candidates (broadcast LDS)

    // Packed sweep over the concatenated index space, fully 32-wide.
    int cnt = 0;  // warp-uniform
    {
        int r = 0;
        int cend = cseg[w][0];
        int kbase = bseg[w][0];
        const int nit = (L + 31) >> 5;
        for (int it = 0; it < nit; ++it) {
            int g = (it << 5) + lane;
            while (g >= cend) {  // monotone cursor: <=9 advances total/lane
                ++r;
                cend = cseg[w][r];
                kbase = bseg[w][r];
            }
            int k = kbase + g;  // invalid lanes (g>=L): r=9 => k=g, safe read
            float4 p = sb[k];
            float ddx = me.x - p.x;
            float ddy = me.y - p.y;
            float ddz = me.z - p.z;
            float d2 = fmaf(ddx, ddx, fmaf(ddy, ddy, ddz * ddz));
            bool inr = (d2 < RGATE) & (g < L);
            unsigned mask = __ballot_sync(0xFFFFFFFFu, inr);
            if (inr) {
                int key = ((int)(d2 * 262144.0f) << 13) | __float_as_int(p.w);
                int pos = cnt + __popc(mask & lt_mask);
                if (pos < CAP) bw[pos] = key;
            }
            cnt += __popc(mask);
        }
    }
    cnt = min(cnt, CAP);
    __syncwarp();

    // Phase 2: top-16 selection; winners parked one per lane.
    const int R = min(cnt, KK);
    int selkey = IMAX;
    if (cnt <= KK) {
        selkey = (lane < cnt) ? bw[lane] : IMAX;
    } else if (cnt <= 64) {
        int v0 = (lane < cnt) ? bw[lane] : IMAX;
        int v1 = (lane + 32 < cnt) ? bw[lane + 32] : IMAX;
        CSWAP(v0, v1);
        for (int r = 0; r < R; ++r) {
            int gmin = __reduce_min_sync(0xFFFFFFFFu, v0);
            bool won = (v0 == gmin);  // unique keys => exactly one winner
            v0 = won ? v1 : v0;
            v1 = won ? IMAX : v1;
            if (lane == r) selkey = gmin;
        }
    } else if (cnt <= 128) {
        int v0 = (lane < cnt) ? bw[lane] : IMAX;
        int v1 = (lane + 32 < cnt) ? bw[lane + 32] : IMAX;
        int v2 = (lane + 64 < cnt) ? bw[lane + 64] : IMAX;
        int v3 = (lane + 96 < cnt) ? bw[lane + 96] : IMAX;
        CSWAP(v0, v1); CSWAP(v2, v3); CSWAP(v0, v2); CSWAP(v1, v3);
        CSWAP(v1, v2);
        for (int r = 0; r < R; ++r) {
            int gmin = __reduce_min_sync(0xFFFFFFFFu, v0);
            bool won = (v0 == gmin);
            v0 = won ? v1 : v0;
            v1 = won ? v2 : v1;
            v2 = won ? v3 : v2;
            v3 = won ? IMAX : v3;
            if (lane == r) selkey = gmin;
        }
    } else if (cnt <= 256) {
        int v0 = (lane < cnt) ? bw[lane] : IMAX;
        int v1 = (lane + 32 < cnt) ? bw[lane + 32] : IMAX;
        int v2 = (lane + 64 < cnt) ? bw[lane + 64] : IMAX;
        int v3 = (lane + 96 < cnt) ? bw[lane + 96] : IMAX;
        int v4 = (lane + 128 < cnt) ? bw[lane + 128] : IMAX;
        int v5 = (lane + 160 < cnt) ? bw[lane + 160] : IMAX;
        int v6 = (lane + 192 < cnt) ? bw[lane + 192] : IMAX;
        int v7 = (lane + 224 < cnt) ? bw[lane + 224] : IMAX;
        // Batcher odd-even merge sort for 8.
        CSWAP(v0, v1); CSWAP(v2, v3); CSWAP(v4, v5); CSWAP(v6, v7);
        CSWAP(v0, v2); CSWAP(v1, v3); CSWAP(v4, v6); CSWAP(v5, v7);
        CSWAP(v1, v2); CSWAP(v5, v6);
        CSWAP(v0, v4); CSWAP(v1, v5); CSWAP(v2, v6); CSWAP(v3, v7);
        CSWAP(v2, v4); CSWAP(v3, v5);
        CSWAP(v1, v2); CSWAP(v3, v4); CSWAP(v5, v6);
        for (int r = 0; r < R; ++r) {
            int gmin = __reduce_min_sync(0xFFFFFFFFu, v0);
            bool won = (v0 == gmin);
            v0 = won ? v1 : v0;
            v1 = won ? v2 : v1;
            v2 = won ? v3 : v2;
            v3 = won ? v4 : v3;
            v4 = won ? v5 : v4;
            v5 = won ? v6 : v5;
            v6 = won ? v7 : v6;
            v7 = won ? IMAX : v7;
            if (lane == r) selkey = gmin;
        }
    } else {
        const int P = (cnt + 31) >> 5;
        for (int r = 0; r < R; ++r) {
            int mymin = IMAX, myidx = 0;
            for (int i = 0; i < P; ++i) {
                int k = lane + (i << 5);
                int vv = (k < cnt) ? bw[k] : IMAX;
                if (vv < mymin) { mymin = vv; myidx = k; }
            }
            int gmin = __reduce_min_sync(0xFFFFFFFFu, mymin);
            if (mymin == gmin && gmin != IMAX) bw[myidx] = IMAX;
            if (lane == r) selkey = gmin;
            __syncwarp();
        }
    }

    // Phase 3: selected lanes compute flow norms; warp + CTA reduce.
    float acc = 0.0f;
    if (selkey != IMAX) {
        const int j = selkey & (NN - 1);  // j==qi (self) => exact 0
        float ddx = flb[3 * qi + 0] - flb[3 * j + 0];
        float ddy = flb[3 * qi + 1] - flb[3 * j + 1];
        float ddz = flb[3 * qi + 2] - flb[3 * j + 2];
        acc = __fsqrt_rn(fmaf(ddx, ddx, fmaf(ddy, ddy, ddz * ddz)));
    }
#pragma unroll
    for (int o = 16; o > 0; o >>= 1)
        acc += __shfl_xor_sync(0xFFFFFFFFu, acc, o);
    if (lane == 0) cpart[w] = acc;
    __syncthreads();
    if (threadIdx.x == 0) {
        float s = 0.0f;
#pragma unroll
        for (int i = 0; i < WPB; ++i) s += cpart[i];
        g_partials[b * NPART + blockIdx.x] = s;
        __threadfence();
        int d = atomicAdd(&g_done, 1);
        lastflag = (d == NCTAS - 1) ? 1 : 0;
    }
    __syncthreads();

    // Last CTA: deterministic fixed-order reduction of all partials.
    if (lastflag) {
        __threadfence();
        float s2 = 0.0f;
#pragma unroll
        for (int i = 0; i < NCTAS / TPB; ++i)
            s2 += g_partials[threadIdx.x + i * TPB];
#pragma unroll
        for (int o = 16; o > 0; o >>= 1)
            s2 += __shfl_xor_sync(0xFFFFFFFFu, s2, o);
        if (lane == 0) cpart[w] = s2;
        __syncthreads();
        if (threadIdx.x == 0) {
            float s3 = 0.0f;
#pragma unroll
            for (int i = 0; i < WPB; ++i) s3 += cpart[i];
            out[0] = s3 * (1.0f / (float)((size_t)BB * NN * KK));
            g_done = 0;  // reset for next graph replay
        }
    }
}

extern "C" void kernel_launch(void* const* d_in, const int* in_sizes, int n_in,
                              void* d_out, int out_size) {
    const float* pc = (const float*)d_in[0];
    const float* flow = (const float*)d_in[1];

    hist_kernel<<<HCTAS, HTPB>>>(pc);
    scatter_kernel<<<HCTAS, HTPB>>>(pc);
    dim3 grid(NN / WPB, BB);
    knn_loss_kernel<<<grid, TPB>>>(flow, (float*)d_out);
}